// round 1
// baseline (speedup 1.0000x reference)
#include <cuda_runtime.h>
#include <cstddef>

#define NSEED 1024
#define NPTS  8192
#define NSAMP 64
#define NDEPTH 4

// Scratch (no allocation allowed)
__device__ float g_feat[2 * NSEED * NDEPTH * NSAMP * 3];   // ~6.3 MB
__device__ float g_vp[2 * NSEED * NDEPTH * 256];           // ~8.4 MB

// ---------------------------------------------------------------------------
// Kernel A: cylinder grouping. One warp per seed. Ordered scan of 8192 points
// with ballot/popc; nested masks (hmax increasing) => early exit on cnt[0]>=64.
// Matches reference top_k semantics: first 64 valid indices in index order,
// remaining slots filled with first-valid point (or point 0 if none valid).
// ---------------------------------------------------------------------------
__global__ __launch_bounds__(256) void group_kernel(
    const float* __restrict__ seed, const float* __restrict__ pc,
    const float* __restrict__ rot)
{
    int gw = (blockIdx.x * blockDim.x + threadIdx.x) >> 5;
    int lane = threadIdx.x & 31;
    if (gw >= 2 * NSEED) return;
    int b = gw >> 10;

    const float* sd = seed + (size_t)gw * 3;
    float sx = sd[0], sy = sd[1], sz = sd[2];
    const float* R = rot + (size_t)gw * 9;
    float r00 = R[0], r01 = R[1], r02 = R[2];
    float r10 = R[3], r11 = R[4], r12 = R[5];
    float r20 = R[6], r21 = R[7], r22 = R[8];
    const float* P = pc + (size_t)b * NPTS * 3;

    int cnt[4] = {0, 0, 0, 0};
    float fx[4], fy[4], fz[4];
    float p0x = 0.f, p0y = 0.f, p0z = 0.f;
    const float hmax[4] = {0.1f, 0.2f, 0.3f, 0.4f};
    float* fb = g_feat + (size_t)gw * NDEPTH * NSAMP * 3;
    unsigned below = (1u << lane) - 1u;

    for (int c = 0; c < NPTS / 32; ++c) {
        int i = c * 32 + lane;
        float px = P[i * 3 + 0], py = P[i * 3 + 1], pz = P[i * 3 + 2];
        float rx = px - sx, ry = py - sy, rz = pz - sz;
        float ax = rx * r00 + ry * r10 + rz * r20;
        float ay = rx * r01 + ry * r11 + rz * r21;
        float az = rx * r02 + ry * r12 + rz * r22;
        float rr = ay * ay + az * az;
        if (c == 0) {
            p0x = __shfl_sync(0xffffffffu, ax, 0);
            p0y = __shfl_sync(0xffffffffu, ay, 0);
            p0z = __shfl_sync(0xffffffffu, az, 0);
        }
        bool base = (ax > -0.2f) && (rr < 0.09f);
        #pragma unroll
        for (int d = 0; d < 4; ++d) {
            bool m = base && (ax < hmax[d]);
            unsigned bal = __ballot_sync(0xffffffffu, m);
            if (bal) {
                if (cnt[d] == 0) {  // capture first valid point for fill
                    int src = __ffs(bal) - 1;
                    fx[d] = __shfl_sync(0xffffffffu, ax, src);
                    fy[d] = __shfl_sync(0xffffffffu, ay, src);
                    fz[d] = __shfl_sync(0xffffffffu, az, src);
                }
                int pos = cnt[d] + __popc(bal & below);
                if (m && pos < NSAMP) {
                    float* o = fb + ((size_t)d * NSAMP + pos) * 3;
                    o[0] = ax; o[1] = ay; o[2] = az;
                }
                cnt[d] += __popc(bal);
            }
        }
        if (cnt[0] >= NSAMP) break;  // masks nested: cnt[0] is the minimum
    }
    #pragma unroll
    for (int d = 0; d < 4; ++d) {
        if (cnt[d] < NSAMP) {
            float vx, vy, vz;
            if (cnt[d] > 0) { vx = fx[d]; vy = fy[d]; vz = fz[d]; }
            else           { vx = p0x;   vy = p0y;   vz = p0z;   }
            for (int pos = cnt[d] + lane; pos < NSAMP; pos += 32) {
                float* o = fb + ((size_t)d * NSAMP + pos) * 3;
                o[0] = vx; o[1] = vy; o[2] = vz;
            }
        }
    }
}

// ---------------------------------------------------------------------------
// Kernel B: SharedMLP [3->64->128->256] + BN(folded) + ReLU + maxpool(64).
// One block per group (8192 blocks, 256 threads). All weights + activations
// in smem (~215KB), register-tiled 8x8 GEMMs, padded strides for bank safety.
// ---------------------------------------------------------------------------
#define SMEM_B_FLOATS (896 + 384 + 64*65 + 128*65 + 64*129 + 256*129)
#define SMEM_B_BYTES  (SMEM_B_FLOATS * 4)

__global__ __launch_bounds__(256) void mlp_kernel(
    const float* __restrict__ cw1, const float* __restrict__ cbn1,
    const float* __restrict__ cw2, const float* __restrict__ cbn2,
    const float* __restrict__ cw3, const float* __restrict__ cbn3)
{
    extern __shared__ float sm[];
    float* sc1  = sm;            // 64
    float* sh1  = sc1 + 64;      // 64
    float* sc2  = sh1 + 64;      // 128
    float* sh2c = sc2 + 128;     // 128
    float* sc3  = sh2c + 128;    // 256
    float* sh3c = sc3 + 256;     // 256
    float* s_w1   = sh3c + 256;  // 192
    float* s_feat = s_w1 + 192;  // 192
    float* s_h1 = s_feat + 192;      // 64 x 65
    float* s_w2 = s_h1 + 64 * 65;    // 128 x 65
    float* s_h2 = s_w2 + 128 * 65;   // 64 x 129
    float* s_w3 = s_h2 + 64 * 129;   // 256 x 129

    int t = threadIdx.x;
    int g = blockIdx.x;

    // Fold BN: scale = g*rsqrt(v+eps), shift = b - m*scale
    if (t < 64) {
        float sc = cbn1[t] * rsqrtf(cbn1[192 + t] + 1e-5f);
        sc1[t] = sc; sh1[t] = cbn1[64 + t] - cbn1[128 + t] * sc;
    }
    if (t < 128) {
        float sc = cbn2[t] * rsqrtf(cbn2[384 + t] + 1e-5f);
        sc2[t] = sc; sh2c[t] = cbn2[128 + t] - cbn2[256 + t] * sc;
    }
    {
        float sc = cbn3[t] * rsqrtf(cbn3[768 + t] + 1e-5f);
        sc3[t] = sc; sh3c[t] = cbn3[256 + t] - cbn3[512 + t] * sc;
    }
    if (t < 192) s_w1[t] = cw1[t];
    {
        const float* fb = g_feat + (size_t)g * 192;
        if (t < 192) s_feat[t] = fb[t];
    }
    for (int idx = t; idx < 128 * 64; idx += 256) {
        int r = idx >> 6, c = idx & 63;
        s_w2[r * 65 + c] = cw2[idx];
    }
    for (int idx = t; idx < 256 * 128; idx += 256) {
        int r = idx >> 7, c = idx & 127;
        s_w3[r * 129 + c] = cw3[idx];
    }
    __syncthreads();

    // Layer 1: 64x64 out, 3-length dots
    #pragma unroll
    for (int q = 0; q < 16; ++q) {
        int o = q * 256 + t;
        int k = o >> 6, j = o & 63;
        float a = s_feat[k * 3 + 0] * s_w1[j * 3 + 0]
                + s_feat[k * 3 + 1] * s_w1[j * 3 + 1]
                + s_feat[k * 3 + 2] * s_w1[j * 3 + 2];
        a = a * sc1[j] + sh1[j];
        s_h1[k * 65 + j] = fmaxf(a, 0.f);
    }
    __syncthreads();

    // Layer 2: (64x64)@(64x128), tile 4 samples x 8 channels
    {
        int tk = t & 15, tj = t >> 4;
        float acc[4][8];
        #pragma unroll
        for (int u = 0; u < 4; ++u)
            #pragma unroll
            for (int v = 0; v < 8; ++v) acc[u][v] = 0.f;
        #pragma unroll 4
        for (int i = 0; i < 64; ++i) {
            float a[4], w[8];
            #pragma unroll
            for (int u = 0; u < 4; ++u) a[u] = s_h1[(tk * 4 + u) * 65 + i];
            #pragma unroll
            for (int v = 0; v < 8; ++v) w[v] = s_w2[(tj * 8 + v) * 65 + i];
            #pragma unroll
            for (int u = 0; u < 4; ++u)
                #pragma unroll
                for (int v = 0; v < 8; ++v) acc[u][v] += a[u] * w[v];
        }
        #pragma unroll
        for (int u = 0; u < 4; ++u)
            #pragma unroll
            for (int v = 0; v < 8; ++v) {
                int k = tk * 4 + u, j = tj * 8 + v;
                float x = acc[u][v] * sc2[j] + sh2c[j];
                s_h2[k * 129 + j] = fmaxf(x, 0.f);
            }
    }
    __syncthreads();

    // Layer 3: (64x128)@(128x256), tile 8x8, fused BN+ReLU+maxpool
    {
        int tk = t & 7, tj = t >> 3;
        float acc[8][8];
        #pragma unroll
        for (int u = 0; u < 8; ++u)
            #pragma unroll
            for (int v = 0; v < 8; ++v) acc[u][v] = 0.f;
        #pragma unroll 4
        for (int i = 0; i < 128; ++i) {
            float a[8], w[8];
            #pragma unroll
            for (int u = 0; u < 8; ++u) a[u] = s_h2[(tk * 8 + u) * 129 + i];
            #pragma unroll
            for (int v = 0; v < 8; ++v) w[v] = s_w3[(tj * 8 + v) * 129 + i];
            #pragma unroll
            for (int u = 0; u < 8; ++u)
                #pragma unroll
                for (int v = 0; v < 8; ++v) acc[u][v] += a[u] * w[v];
        }
        float mx[8];
        #pragma unroll
        for (int v = 0; v < 8; ++v) {
            int j = tj * 8 + v;
            float m = -1e30f;
            #pragma unroll
            for (int u = 0; u < 8; ++u) {
                float x = fmaxf(acc[u][v] * sc3[j] + sh3c[j], 0.f);
                m = fmaxf(m, x);
            }
            mx[v] = m;
        }
        // reduce max across the 8 threads sharing tj (segments of 8 lanes)
        #pragma unroll
        for (int off = 4; off > 0; off >>= 1)
            #pragma unroll
            for (int v = 0; v < 8; ++v)
                mx[v] = fmaxf(mx[v], __shfl_down_sync(0xffffffffu, mx[v], off, 8));
        if (tk == 0) {
            #pragma unroll
            for (int v = 0; v < 8; ++v)
                g_vp[(size_t)g * 256 + tj * 8 + v] = mx[v];
        }
    }
}

// ---------------------------------------------------------------------------
// Kernel C: both heads (op: 256->128->128->36, tol: 256->128->128->12).
// One block = 8 rows, 256 threads (op channels 0..127, tol 128..255),
// weight tiles staged to smem. Writes final transposed output.
// ---------------------------------------------------------------------------
#define SMEM_C_FLOATS (2048*3 + 256*4 + 256*33 + 48*129)
#define SMEM_C_BYTES  (SMEM_C_FLOATS * 4)

__global__ __launch_bounds__(256) void head_kernel(
    const float* __restrict__ ow1, const float* __restrict__ ob1, const float* __restrict__ obn1,
    const float* __restrict__ ow2, const float* __restrict__ ob2, const float* __restrict__ obn2,
    const float* __restrict__ ow3, const float* __restrict__ ob3,
    const float* __restrict__ tw1, const float* __restrict__ tb1, const float* __restrict__ tbn1,
    const float* __restrict__ tw2, const float* __restrict__ tb2, const float* __restrict__ tbn2,
    const float* __restrict__ tw3, const float* __restrict__ tb3,
    float* __restrict__ out)
{
    extern __shared__ float sm[];
    float* s_vp = sm;              // 8 x 256
    float* s_h1 = s_vp + 2048;     // 8 x 256 (op|tol)
    float* s_h2 = s_h1 + 2048;     // 8 x 256
    float* sA1  = s_h2 + 2048;     // 256
    float* hA1  = sA1 + 256;
    float* sA2  = hA1 + 256;
    float* hA2  = sA2 + 256;
    float* s_wt = hA2 + 256;       // 256 x 33
    float* s_w3 = s_wt + 256 * 33; // 48 x 129

    int t = threadIdx.x;
    int row0 = blockIdx.x * 8;

    {   // folded BN (+bias into shift): shift = (b_lin - m)*scale + b_bn
        int c = t & 127;
        if (t < 128) {
            float sc = obn1[c] * rsqrtf(obn1[384 + c] + 1e-5f);
            sA1[t] = sc; hA1[t] = (ob1[c] - obn1[256 + c]) * sc + obn1[128 + c];
            float s2 = obn2[c] * rsqrtf(obn2[384 + c] + 1e-5f);
            sA2[t] = s2; hA2[t] = (ob2[c] - obn2[256 + c]) * s2 + obn2[128 + c];
        } else {
            float sc = tbn1[c] * rsqrtf(tbn1[384 + c] + 1e-5f);
            sA1[t] = sc; hA1[t] = (tb1[c] - tbn1[256 + c]) * sc + tbn1[128 + c];
            float s2 = tbn2[c] * rsqrtf(tbn2[384 + c] + 1e-5f);
            sA2[t] = s2; hA2[t] = (tb2[c] - tbn2[256 + c]) * s2 + tbn2[128 + c];
        }
    }
    for (int idx = t; idx < 2048; idx += 256)
        s_vp[idx] = g_vp[(size_t)row0 * 256 + idx];
    for (int idx = t; idx < 48 * 128; idx += 256) {
        int r = idx >> 7, c = idx & 127;
        s_w3[r * 129 + c] = (r < 36) ? ow3[r * 128 + c] : tw3[(r - 36) * 128 + c];
    }
    __syncthreads();

    float acc[8];
    // ---- Layer 1 (256 -> 128 per head) ----
    #pragma unroll
    for (int r = 0; r < 8; ++r) acc[r] = 0.f;
    for (int i0 = 0; i0 < 256; i0 += 32) {
        #pragma unroll
        for (int q = 0; q < 32; ++q) {
            int idx = q * 256 + t; int r = idx >> 5, c = idx & 31;
            s_wt[r * 33 + c] = (r < 128) ? ow1[r * 256 + i0 + c]
                                         : tw1[(r - 128) * 256 + i0 + c];
        }
        __syncthreads();
        #pragma unroll
        for (int i = 0; i < 32; ++i) {
            float w = s_wt[t * 33 + i];
            #pragma unroll
            for (int r = 0; r < 8; ++r) acc[r] += s_vp[r * 256 + i0 + i] * w;
        }
        __syncthreads();
    }
    #pragma unroll
    for (int r = 0; r < 8; ++r)
        s_h1[r * 256 + t] = fmaxf(acc[r] * sA1[t] + hA1[t], 0.f);
    __syncthreads();

    // ---- Layer 2 (128 -> 128 per head) ----
    #pragma unroll
    for (int r = 0; r < 8; ++r) acc[r] = 0.f;
    int hbase = t & 128;
    for (int i0 = 0; i0 < 128; i0 += 32) {
        #pragma unroll
        for (int q = 0; q < 32; ++q) {
            int idx = q * 256 + t; int r = idx >> 5, c = idx & 31;
            s_wt[r * 33 + c] = (r < 128) ? ow2[r * 128 + i0 + c]
                                         : tw2[(r - 128) * 128 + i0 + c];
        }
        __syncthreads();
        #pragma unroll
        for (int i = 0; i < 32; ++i) {
            float w = s_wt[t * 33 + i];
            #pragma unroll
            for (int r = 0; r < 8; ++r) acc[r] += s_h1[r * 256 + hbase + i0 + i] * w;
        }
        __syncthreads();
    }
    #pragma unroll
    for (int r = 0; r < 8; ++r)
        s_h2[r * 256 + t] = fmaxf(acc[r] * sA2[t] + hA2[t], 0.f);
    __syncthreads();

    // ---- Layer 3 (128 -> 36|12), write transposed output ----
    {
        int r = t >> 5, c0 = t & 31;
        #pragma unroll
        for (int half = 0; half < 2; ++half) {
            int cc = c0 + half * 32;
            if (cc < 48) {
                int hb = (cc < 36) ? 0 : 128;
                float a = 0.f;
                #pragma unroll 8
                for (int i = 0; i < 128; ++i)
                    a += s_h2[r * 256 + hb + i] * s_w3[cc * 129 + i];
                a += (cc < 36) ? ob3[cc] : tb3[cc - 36];
                int row = row0 + r;
                int b = row >> 12, rr = row & 4095, s = rr >> 2, d = rr & 3;
                out[(((size_t)b * 48 + cc) * 1024 + s) * 4 + d] = a;
            }
        }
    }
}

// ---------------------------------------------------------------------------
extern "C" void kernel_launch(void* const* d_in, const int* in_sizes, int n_in,
                              void* d_out, int out_size)
{
    (void)in_sizes; (void)n_in; (void)out_size;
    const float* seed = (const float*)d_in[0];
    const float* pc   = (const float*)d_in[1];
    const float* rot  = (const float*)d_in[2];
    const float* cw1  = (const float*)d_in[3];
    const float* cbn1 = (const float*)d_in[4];
    const float* cw2  = (const float*)d_in[5];
    const float* cbn2 = (const float*)d_in[6];
    const float* cw3  = (const float*)d_in[7];
    const float* cbn3 = (const float*)d_in[8];
    const float* ow1  = (const float*)d_in[9];
    const float* ob1  = (const float*)d_in[10];
    const float* obn1 = (const float*)d_in[11];
    const float* ow2  = (const float*)d_in[12];
    const float* ob2  = (const float*)d_in[13];
    const float* obn2 = (const float*)d_in[14];
    const float* ow3  = (const float*)d_in[15];
    const float* ob3  = (const float*)d_in[16];
    const float* tw1  = (const float*)d_in[17];
    const float* tb1  = (const float*)d_in[18];
    const float* tbn1 = (const float*)d_in[19];
    const float* tw2  = (const float*)d_in[20];
    const float* tb2  = (const float*)d_in[21];
    const float* tbn2 = (const float*)d_in[22];
    const float* tw3  = (const float*)d_in[23];
    const float* tb3  = (const float*)d_in[24];
    float* out = (float*)d_out;

    cudaFuncSetAttribute(mlp_kernel,  cudaFuncAttributeMaxDynamicSharedMemorySize, SMEM_B_BYTES);
    cudaFuncSetAttribute(head_kernel, cudaFuncAttributeMaxDynamicSharedMemorySize, SMEM_C_BYTES);

    group_kernel<<<256, 256>>>(seed, pc, rot);
    mlp_kernel<<<2 * NSEED * NDEPTH, 256, SMEM_B_BYTES>>>(cw1, cbn1, cw2, cbn2, cw3, cbn3);
    head_kernel<<<2 * NSEED * NDEPTH / 8, 256, SMEM_C_BYTES>>>(
        ow1, ob1, obn1, ow2, ob2, obn2, ow3, ob3,
        tw1, tb1, tbn1, tw2, tb2, tbn2, tw3, tb3, out);
}

// round 2
// speedup vs baseline: 1.4607x; 1.4607x over previous
#include <cuda_runtime.h>
#include <cstddef>

#define NSEED 1024
#define NPTS  8192
#define NSAMP 64
#define NDEPTH 4

typedef unsigned long long ull;

// Scratch (no allocation allowed)
__device__ float g_feat[2 * NSEED * NDEPTH * NSAMP * 3];   // ~6.3 MB
__device__ float g_vp[2 * NSEED * NDEPTH * 256];           // ~8.4 MB

// ---------------- packed f32x2 helpers --------------------------------------
__device__ __forceinline__ void fma2(ull& d, ull a, ull b) {
    asm("fma.rn.f32x2 %0, %1, %2, %0;" : "+l"(d) : "l"(a), "l"(b));
}
__device__ __forceinline__ ull pack2(float lo, float hi) {
    ull r; asm("mov.b64 %0, {%1, %2};" : "=l"(r) : "f"(lo), "f"(hi)); return r;
}
__device__ __forceinline__ void unpack2(ull v, float& lo, float& hi) {
    asm("mov.b64 {%0, %1}, %2;" : "=f"(lo), "=f"(hi) : "l"(v));
}
__device__ __forceinline__ void cpasync16(void* sdst, const void* gsrc) {
    unsigned s = (unsigned)__cvta_generic_to_shared(sdst);
    asm volatile("cp.async.ca.shared.global [%0], [%1], 16;" :: "r"(s), "l"(gsrc));
}
__device__ __forceinline__ void cpcommit() { asm volatile("cp.async.commit_group;"); }

// ---------------------------------------------------------------------------
// Kernel A: cylinder grouping. One warp per seed, ordered ballot/popc scan,
// double-buffered point prefetch to hide LDG latency.
// ---------------------------------------------------------------------------
__global__ __launch_bounds__(256) void group_kernel(
    const float* __restrict__ seed, const float* __restrict__ pc,
    const float* __restrict__ rot)
{
    int gw = (blockIdx.x * blockDim.x + threadIdx.x) >> 5;
    int lane = threadIdx.x & 31;
    if (gw >= 2 * NSEED) return;
    int b = gw >> 10;

    const float* sd = seed + (size_t)gw * 3;
    float sx = sd[0], sy = sd[1], sz = sd[2];
    const float* R = rot + (size_t)gw * 9;
    float r00 = R[0], r01 = R[1], r02 = R[2];
    float r10 = R[3], r11 = R[4], r12 = R[5];
    float r20 = R[6], r21 = R[7], r22 = R[8];
    const float* P = pc + (size_t)b * NPTS * 3;

    int cnt[4] = {0, 0, 0, 0};
    float fx[4], fy[4], fz[4];
    float p0x = 0.f, p0y = 0.f, p0z = 0.f;
    const float hmax[4] = {0.1f, 0.2f, 0.3f, 0.4f};
    float* fb = g_feat + (size_t)gw * NDEPTH * NSAMP * 3;
    unsigned below = (1u << lane) - 1u;

    // prefetch chunk 0
    float px = P[lane * 3 + 0], py = P[lane * 3 + 1], pz = P[lane * 3 + 2];

    for (int c = 0; c < NPTS / 32; ++c) {
        float npx = 0.f, npy = 0.f, npz = 0.f;
        if (c + 1 < NPTS / 32) {
            int ni = (c + 1) * 32 + lane;
            npx = P[ni * 3 + 0]; npy = P[ni * 3 + 1]; npz = P[ni * 3 + 2];
        }
        float rx = px - sx, ry = py - sy, rz = pz - sz;
        float ax = rx * r00 + ry * r10 + rz * r20;
        float ay = rx * r01 + ry * r11 + rz * r21;
        float az = rx * r02 + ry * r12 + rz * r22;
        float rr = ay * ay + az * az;
        if (c == 0) {
            p0x = __shfl_sync(0xffffffffu, ax, 0);
            p0y = __shfl_sync(0xffffffffu, ay, 0);
            p0z = __shfl_sync(0xffffffffu, az, 0);
        }
        bool base = (ax > -0.2f) && (rr < 0.09f);
        #pragma unroll
        for (int d = 0; d < 4; ++d) {
            bool m = base && (ax < hmax[d]);
            unsigned bal = __ballot_sync(0xffffffffu, m);
            if (bal) {
                if (cnt[d] == 0) {
                    int src = __ffs(bal) - 1;
                    fx[d] = __shfl_sync(0xffffffffu, ax, src);
                    fy[d] = __shfl_sync(0xffffffffu, ay, src);
                    fz[d] = __shfl_sync(0xffffffffu, az, src);
                }
                int pos = cnt[d] + __popc(bal & below);
                if (m && pos < NSAMP) {
                    float* o = fb + ((size_t)d * NSAMP + pos) * 3;
                    o[0] = ax; o[1] = ay; o[2] = az;
                }
                cnt[d] += __popc(bal);
            }
        }
        px = npx; py = npy; pz = npz;
        if (cnt[0] >= NSAMP) break;  // nested masks: cnt[0] is the minimum
    }
    #pragma unroll
    for (int d = 0; d < 4; ++d) {
        if (cnt[d] < NSAMP) {
            float vx, vy, vz;
            if (cnt[d] > 0) { vx = fx[d]; vy = fy[d]; vz = fz[d]; }
            else           { vx = p0x;   vy = p0y;   vz = p0z;   }
            for (int pos = cnt[d] + lane; pos < NSAMP; pos += 32) {
                float* o = fb + ((size_t)d * NSAMP + pos) * 3;
                o[0] = vx; o[1] = vy; o[2] = vz;
            }
        }
    }
}

// ---------------------------------------------------------------------------
// Kernel B: SharedMLP [3->64->128->256] + BN + ReLU + maxpool, packed f32x2.
// Activations transposed (channel rows, samples contiguous) with a 2-float
// gap at sample 32 (row stride 72) -> conflict-free sample-pair LDS.64.
// Weights [out][in] with +16B pad per 4 rows -> conflict-free w broadcasts
// AND 16B-aligned rows for cp.async staging (overlapped with layers 1-2).
// ---------------------------------------------------------------------------
// smem float offsets
#define OFF_SC1   0        // 64
#define OFF_SH1   64       // 64
#define OFF_SC2   128      // 128
#define OFF_SH2   256      // 128
#define OFF_SC3   384      // 256
#define OFF_SH3   640      // 256
#define OFF_W1    896      // 192
#define OFF_FEAT  1088     // 192
#define OFF_H1T   1280     // 64*72  = 4608
#define OFF_H2T   5888     // 128*72 = 9216
#define OFF_W2S   15104    // 32 groups * 260 = 8320
#define OFF_W3S   23424    // 64 groups * 516 = 33024
#define SMEM_B_FLOATS 56448
#define SMEM_B_BYTES  (SMEM_B_FLOATS * 4)   // 225792 B

__device__ __forceinline__ int koff(int k) { return k + (k >= 32 ? 2 : 0); }

__global__ __launch_bounds__(256) void mlp_kernel(
    const float* __restrict__ cw1, const float* __restrict__ cbn1,
    const float* __restrict__ cw2, const float* __restrict__ cbn2,
    const float* __restrict__ cw3, const float* __restrict__ cbn3)
{
    extern __shared__ float sm[];
    int t = threadIdx.x;
    int g = blockIdx.x;

    // --- async weight staging (w2 group, then w3 group) ---
    // w2: 128x64, element (j,i) -> (j>>2)*260 + (j&3)*64 + i
    #pragma unroll
    for (int q = 0; q < 8; ++q) {
        int e = q * 256 + t;          // 16B chunk id, 2048 total
        int j = e >> 4, c = e & 15;
        cpasync16(sm + OFF_W2S + (j >> 2) * 260 + (j & 3) * 64 + c * 4,
                  cw2 + j * 64 + c * 4);
    }
    cpcommit();
    // w3: 256x128, element (j,i) -> (j>>2)*516 + (j&3)*128 + i
    #pragma unroll
    for (int q = 0; q < 32; ++q) {
        int e = q * 256 + t;          // 8192 chunks
        int j = e >> 5, c = e & 31;
        cpasync16(sm + OFF_W3S + (j >> 2) * 516 + (j & 3) * 128 + c * 4,
                  cw3 + j * 128 + c * 4);
    }
    cpcommit();

    // --- small staging: folded BN consts, w1, features ---
    if (t < 64) {
        float sc = cbn1[t] * rsqrtf(cbn1[192 + t] + 1e-5f);
        sm[OFF_SC1 + t] = sc; sm[OFF_SH1 + t] = cbn1[64 + t] - cbn1[128 + t] * sc;
    }
    if (t < 128) {
        float sc = cbn2[t] * rsqrtf(cbn2[384 + t] + 1e-5f);
        sm[OFF_SC2 + t] = sc; sm[OFF_SH2 + t] = cbn2[128 + t] - cbn2[256 + t] * sc;
    }
    {
        float sc = cbn3[t] * rsqrtf(cbn3[768 + t] + 1e-5f);
        sm[OFF_SC3 + t] = sc; sm[OFF_SH3 + t] = cbn3[256 + t] - cbn3[512 + t] * sc;
    }
    if (t < 192) sm[OFF_W1 + t] = cw1[t];
    if (t < 192) sm[OFF_FEAT + t] = g_feat[(size_t)g * 192 + t];
    __syncthreads();

    // --- Layer 1: 64 samples x 64 ch, write transposed h1t[j][k] ---
    #pragma unroll
    for (int q = 0; q < 16; ++q) {
        int o = q * 256 + t;
        int k = o >> 6, j = o & 63;
        float a = sm[OFF_FEAT + k * 3 + 0] * sm[OFF_W1 + j * 3 + 0]
                + sm[OFF_FEAT + k * 3 + 1] * sm[OFF_W1 + j * 3 + 1]
                + sm[OFF_FEAT + k * 3 + 2] * sm[OFF_W1 + j * 3 + 2];
        a = a * sm[OFF_SC1 + j] + sm[OFF_SH1 + j];
        sm[OFF_H1T + j * 72 + koff(k)] = fmaxf(a, 0.f);
    }
    asm volatile("cp.async.wait_group 1;");   // w2 resident
    __syncthreads();

    // --- Layer 2: (64x64)@(64x128), f32x2. tile: 4 samples (2 pairs) x 8 ch
    {
        int tk = t & 15, tj = t >> 4;
        int ka[2]; ka[0] = koff(tk * 4); ka[1] = koff(tk * 4 + 2);
        int wo[8];
        #pragma unroll
        for (int v = 0; v < 8; ++v) {
            int j = tj * 8 + v;
            wo[v] = OFF_W2S + (j >> 2) * 260 + (j & 3) * 64;
        }
        ull acc[2][8];
        #pragma unroll
        for (int u = 0; u < 2; ++u)
            #pragma unroll
            for (int v = 0; v < 8; ++v) acc[u][v] = 0ull;
        #pragma unroll 4
        for (int i = 0; i < 64; ++i) {
            ull a0 = *(const ull*)(sm + OFF_H1T + i * 72 + ka[0]);
            ull a1 = *(const ull*)(sm + OFF_H1T + i * 72 + ka[1]);
            #pragma unroll
            for (int v = 0; v < 8; ++v) {
                float w = sm[wo[v] + i];
                ull w2 = pack2(w, w);
                fma2(acc[0][v], a0, w2);
                fma2(acc[1][v], a1, w2);
            }
        }
        #pragma unroll
        for (int v = 0; v < 8; ++v) {
            int j = tj * 8 + v;
            float sc = sm[OFF_SC2 + j], sh = sm[OFF_SH2 + j];
            #pragma unroll
            for (int u = 0; u < 2; ++u) {
                float lo, hi; unpack2(acc[u][v], lo, hi);
                lo = fmaxf(lo * sc + sh, 0.f);
                hi = fmaxf(hi * sc + sh, 0.f);
                *(ull*)(sm + OFF_H2T + j * 72 + ka[u]) = pack2(lo, hi);
            }
        }
    }
    asm volatile("cp.async.wait_group 0;");   // w3 resident
    __syncthreads();

    // --- Layer 3: (64x128)@(128x256), f32x2. tile: 8 samples (4 pairs) x 8 ch
    {
        int tk = t & 7, tj = t >> 3;
        int ka[4];
        #pragma unroll
        for (int u = 0; u < 4; ++u) ka[u] = koff(tk * 8 + 2 * u);
        int wo[8];
        #pragma unroll
        for (int v = 0; v < 8; ++v) {
            int j = tj * 8 + v;
            wo[v] = OFF_W3S + (j >> 2) * 516 + (j & 3) * 128;
        }
        ull acc[4][8];
        #pragma unroll
        for (int u = 0; u < 4; ++u)
            #pragma unroll
            for (int v = 0; v < 8; ++v) acc[u][v] = 0ull;
        #pragma unroll 4
        for (int i = 0; i < 128; ++i) {
            ull a[4];
            #pragma unroll
            for (int u = 0; u < 4; ++u)
                a[u] = *(const ull*)(sm + OFF_H2T + i * 72 + ka[u]);
            #pragma unroll
            for (int v = 0; v < 8; ++v) {
                float w = sm[wo[v] + i];
                ull w2 = pack2(w, w);
                #pragma unroll
                for (int u = 0; u < 4; ++u) fma2(acc[u][v], a[u], w2);
            }
        }
        // BN + ReLU + maxpool over 64 samples
        float mx[8];
        #pragma unroll
        for (int v = 0; v < 8; ++v) {
            int j = tj * 8 + v;
            float sc = sm[OFF_SC3 + j], sh = sm[OFF_SH3 + j];
            float m = -1e30f;
            #pragma unroll
            for (int u = 0; u < 4; ++u) {
                float lo, hi; unpack2(acc[u][v], lo, hi);
                m = fmaxf(m, fmaxf(lo * sc + sh, 0.f));
                m = fmaxf(m, fmaxf(hi * sc + sh, 0.f));
            }
            mx[v] = m;
        }
        #pragma unroll
        for (int off = 4; off > 0; off >>= 1)
            #pragma unroll
            for (int v = 0; v < 8; ++v)
                mx[v] = fmaxf(mx[v], __shfl_down_sync(0xffffffffu, mx[v], off, 8));
        if (tk == 0) {
            #pragma unroll
            for (int v = 0; v < 8; ++v)
                g_vp[(size_t)g * 256 + tj * 8 + v] = mx[v];
        }
    }
}

// ---------------------------------------------------------------------------
// Kernel C: both heads (op: 256->128->128->36, tol: 256->128->128->12).
// ---------------------------------------------------------------------------
#define SMEM_C_FLOATS (2048*3 + 256*4 + 256*33 + 48*129)
#define SMEM_C_BYTES  (SMEM_C_FLOATS * 4)

__global__ __launch_bounds__(256) void head_kernel(
    const float* __restrict__ ow1, const float* __restrict__ ob1, const float* __restrict__ obn1,
    const float* __restrict__ ow2, const float* __restrict__ ob2, const float* __restrict__ obn2,
    const float* __restrict__ ow3, const float* __restrict__ ob3,
    const float* __restrict__ tw1, const float* __restrict__ tb1, const float* __restrict__ tbn1,
    const float* __restrict__ tw2, const float* __restrict__ tb2, const float* __restrict__ tbn2,
    const float* __restrict__ tw3, const float* __restrict__ tb3,
    float* __restrict__ out)
{
    extern __shared__ float sm[];
    float* s_vp = sm;              // 8 x 256
    float* s_h1 = s_vp + 2048;
    float* s_h2 = s_h1 + 2048;
    float* sA1  = s_h2 + 2048;
    float* hA1  = sA1 + 256;
    float* sA2  = hA1 + 256;
    float* hA2  = sA2 + 256;
    float* s_wt = hA2 + 256;       // 256 x 33
    float* s_w3 = s_wt + 256 * 33; // 48 x 129

    int t = threadIdx.x;
    int row0 = blockIdx.x * 8;

    {
        int c = t & 127;
        if (t < 128) {
            float sc = obn1[c] * rsqrtf(obn1[384 + c] + 1e-5f);
            sA1[t] = sc; hA1[t] = (ob1[c] - obn1[256 + c]) * sc + obn1[128 + c];
            float s2 = obn2[c] * rsqrtf(obn2[384 + c] + 1e-5f);
            sA2[t] = s2; hA2[t] = (ob2[c] - obn2[256 + c]) * s2 + obn2[128 + c];
        } else {
            float sc = tbn1[c] * rsqrtf(tbn1[384 + c] + 1e-5f);
            sA1[t] = sc; hA1[t] = (tb1[c] - tbn1[256 + c]) * sc + tbn1[128 + c];
            float s2 = tbn2[c] * rsqrtf(tbn2[384 + c] + 1e-5f);
            sA2[t] = s2; hA2[t] = (tb2[c] - tbn2[256 + c]) * s2 + tbn2[128 + c];
        }
    }
    for (int idx = t; idx < 2048; idx += 256)
        s_vp[idx] = g_vp[(size_t)row0 * 256 + idx];
    for (int idx = t; idx < 48 * 128; idx += 256) {
        int r = idx >> 7, c = idx & 127;
        s_w3[r * 129 + c] = (r < 36) ? ow3[r * 128 + c] : tw3[(r - 36) * 128 + c];
    }
    __syncthreads();

    float acc[8];
    // ---- Layer 1 (256 -> 128 per head) ----
    #pragma unroll
    for (int r = 0; r < 8; ++r) acc[r] = 0.f;
    for (int i0 = 0; i0 < 256; i0 += 32) {
        #pragma unroll
        for (int q = 0; q < 32; ++q) {
            int idx = q * 256 + t; int r = idx >> 5, c = idx & 31;
            s_wt[r * 33 + c] = (r < 128) ? ow1[r * 256 + i0 + c]
                                         : tw1[(r - 128) * 256 + i0 + c];
        }
        __syncthreads();
        #pragma unroll
        for (int i = 0; i < 32; ++i) {
            float w = s_wt[t * 33 + i];
            #pragma unroll
            for (int r = 0; r < 8; ++r) acc[r] += s_vp[r * 256 + i0 + i] * w;
        }
        __syncthreads();
    }
    #pragma unroll
    for (int r = 0; r < 8; ++r)
        s_h1[r * 256 + t] = fmaxf(acc[r] * sA1[t] + hA1[t], 0.f);
    __syncthreads();

    // ---- Layer 2 (128 -> 128 per head) ----
    #pragma unroll
    for (int r = 0; r < 8; ++r) acc[r] = 0.f;
    int hbase = t & 128;
    for (int i0 = 0; i0 < 128; i0 += 32) {
        #pragma unroll
        for (int q = 0; q < 32; ++q) {
            int idx = q * 256 + t; int r = idx >> 5, c = idx & 31;
            s_wt[r * 33 + c] = (r < 128) ? ow2[r * 128 + i0 + c]
                                         : tw2[(r - 128) * 128 + i0 + c];
        }
        __syncthreads();
        #pragma unroll
        for (int i = 0; i < 32; ++i) {
            float w = s_wt[t * 33 + i];
            #pragma unroll
            for (int r = 0; r < 8; ++r) acc[r] += s_h1[r * 256 + hbase + i0 + i] * w;
        }
        __syncthreads();
    }
    #pragma unroll
    for (int r = 0; r < 8; ++r)
        s_h2[r * 256 + t] = fmaxf(acc[r] * sA2[t] + hA2[t], 0.f);
    __syncthreads();

    // ---- Layer 3 (128 -> 36|12), transposed output ----
    {
        int r = t >> 5, c0 = t & 31;
        #pragma unroll
        for (int half = 0; half < 2; ++half) {
            int cc = c0 + half * 32;
            if (cc < 48) {
                int hb = (cc < 36) ? 0 : 128;
                float a = 0.f;
                #pragma unroll 8
                for (int i = 0; i < 128; ++i)
                    a += s_h2[r * 256 + hb + i] * s_w3[cc * 129 + i];
                a += (cc < 36) ? ob3[cc] : tb3[cc - 36];
                int row = row0 + r;
                int b = row >> 12, rr = row & 4095, s = rr >> 2, d = rr & 3;
                out[(((size_t)b * 48 + cc) * 1024 + s) * 4 + d] = a;
            }
        }
    }
}

// ---------------------------------------------------------------------------
extern "C" void kernel_launch(void* const* d_in, const int* in_sizes, int n_in,
                              void* d_out, int out_size)
{
    (void)in_sizes; (void)n_in; (void)out_size;
    const float* seed = (const float*)d_in[0];
    const float* pc   = (const float*)d_in[1];
    const float* rot  = (const float*)d_in[2];
    const float* cw1  = (const float*)d_in[3];
    const float* cbn1 = (const float*)d_in[4];
    const float* cw2  = (const float*)d_in[5];
    const float* cbn2 = (const float*)d_in[6];
    const float* cw3  = (const float*)d_in[7];
    const float* cbn3 = (const float*)d_in[8];
    const float* ow1  = (const float*)d_in[9];
    const float* ob1  = (const float*)d_in[10];
    const float* obn1 = (const float*)d_in[11];
    const float* ow2  = (const float*)d_in[12];
    const float* ob2  = (const float*)d_in[13];
    const float* obn2 = (const float*)d_in[14];
    const float* ow3  = (const float*)d_in[15];
    const float* ob3  = (const float*)d_in[16];
    const float* tw1  = (const float*)d_in[17];
    const float* tb1  = (const float*)d_in[18];
    const float* tbn1 = (const float*)d_in[19];
    const float* tw2  = (const float*)d_in[20];
    const float* tb2  = (const float*)d_in[21];
    const float* tbn2 = (const float*)d_in[22];
    const float* tw3  = (const float*)d_in[23];
    const float* tb3  = (const float*)d_in[24];
    float* out = (float*)d_out;

    cudaFuncSetAttribute(mlp_kernel,  cudaFuncAttributeMaxDynamicSharedMemorySize, SMEM_B_BYTES);
    cudaFuncSetAttribute(head_kernel, cudaFuncAttributeMaxDynamicSharedMemorySize, SMEM_C_BYTES);

    group_kernel<<<256, 256>>>(seed, pc, rot);
    mlp_kernel<<<2 * NSEED * NDEPTH, 256, SMEM_B_BYTES>>>(cw1, cbn1, cw2, cbn2, cw3, cbn3);
    head_kernel<<<2 * NSEED * NDEPTH / 8, 256, SMEM_C_BYTES>>>(
        ow1, ob1, obn1, ow2, ob2, obn2, ow3, ob3,
        tw1, tb1, tbn1, tw2, tb2, tbn2, tw3, tb3, out);
}